// round 1
// baseline (speedup 1.0000x reference)
#include <cuda_runtime.h>
#include <stdint.h>

// ---- SOM constants (match reference) ----
#define GM 64
#define GN 64
#define NODES 4096
#define FEATS 256
#define BATCH 1024
#define SIGMA_F 70.4f        // max(M,N) * 1.1
#define TOTAL_ITER_F 100000.0f

// ---- device scratch (no allocations allowed) ----
__device__ unsigned long long g_best[BATCH];
__device__ int   g_bmu[BATCH];
__device__ float g_w2[NODES];
__device__ float g_params[3];   // [0]=lr, [1]=1/(2 r^2), [2]=r^2

// ============================================================
// K0: reset argmin keys + compute decayed lr / radius params
// ============================================================
__global__ void k_init(const int* __restrict__ iter) {
    int t = blockIdx.x * blockDim.x + threadIdx.x;
    if (t < BATCH) g_best[t] = 0xFFFFFFFFFFFFFFFFull;
    if (t == 0) {
        float lambda_g = TOTAL_ITER_F / SIGMA_F;
        float decay    = expf(-(float)iter[0] / lambda_g);
        float radius   = SIGMA_F * decay + 1e-6f;
        g_params[0] = 0.5f * decay;
        g_params[1] = 1.0f / (2.0f * radius * radius);
        g_params[2] = radius * radius;
    }
}

// ============================================================
// K1: w2[n] = sum_d w[n,d]^2   (one warp per node)
// ============================================================
__global__ void k_w2(const float* __restrict__ w) {
    int warp = threadIdx.x >> 5, lane = threadIdx.x & 31;
    int n = blockIdx.x * 8 + warp;
    const float4* row = (const float4*)(w + (size_t)n * FEATS);
    float s = 0.0f;
    #pragma unroll
    for (int i = 0; i < 2; i++) {
        float4 v = row[lane + 32 * i];
        s += v.x * v.x + v.y * v.y + v.z * v.z + v.w * v.w;
    }
    #pragma unroll
    for (int o = 16; o; o >>= 1) s += __shfl_xor_sync(0xFFFFFFFFu, s, o);
    if (lane == 0) g_w2[n] = s;
}

// ============================================================
// K2: distance GEMM (B x NODES x FEATS) fused with row argmin.
// dist = w2[n] - 2 * x.w  (x^2 term is row-constant -> argmin invariant)
// Block: 64 samples x 64 nodes, 256 threads, 4x4 per-thread tile.
// Argmin via packed (monotone-uint(dist) << 32 | node) atomicMin -> ties
// resolve to lowest node index, order-independent (graph-safe).
// ============================================================
__global__ void __launch_bounds__(256) k_bmu(const float* __restrict__ x,
                                             const float* __restrict__ w) {
    __shared__ float xs[64][33];
    __shared__ float ws[64][33];
    int tid = threadIdx.x;
    int n0 = blockIdx.x * 64;
    int m0 = blockIdx.y * 64;
    int ty = tid >> 4, tx = tid & 15;

    float acc[4][4];
    #pragma unroll
    for (int i = 0; i < 4; i++)
        #pragma unroll
        for (int j = 0; j < 4; j++) acc[i][j] = 0.0f;

    int r0 = tid >> 5, c = tid & 31;
    for (int k0 = 0; k0 < FEATS; k0 += 32) {
        #pragma unroll
        for (int i = 0; i < 8; i++) {
            int r = r0 + 8 * i;
            xs[r][c] = x[(size_t)(m0 + r) * FEATS + k0 + c];
            ws[r][c] = w[(size_t)(n0 + r) * FEATS + k0 + c];
        }
        __syncthreads();
        #pragma unroll
        for (int k = 0; k < 32; k++) {
            float am[4], bn[4];
            #pragma unroll
            for (int i = 0; i < 4; i++) am[i] = xs[ty * 4 + i][k];
            #pragma unroll
            for (int j = 0; j < 4; j++) bn[j] = ws[tx * 4 + j][k];
            #pragma unroll
            for (int i = 0; i < 4; i++)
                #pragma unroll
                for (int j = 0; j < 4; j++) acc[i][j] += am[i] * bn[j];
        }
        __syncthreads();
    }

    // epilogue: per-sample local argmin over this block's 64 nodes
    #pragma unroll
    for (int i = 0; i < 4; i++) {
        float best = __int_as_float(0x7F800000);  // +inf
        int bestn = 0;
        #pragma unroll
        for (int j = 0; j < 4; j++) {
            int n = n0 + tx * 4 + j;
            float d = g_w2[n] - 2.0f * acc[i][j];
            if (d < best) { best = d; bestn = n; }
        }
        // reduce across the 16 tx lanes (offsets <=8 stay within half-warp)
        #pragma unroll
        for (int o = 8; o; o >>= 1) {
            float od = __shfl_xor_sync(0xFFFFFFFFu, best, o);
            int   on = __shfl_xor_sync(0xFFFFFFFFu, bestn, o);
            if (od < best || (od == best && on < bestn)) { best = od; bestn = on; }
        }
        if (tx == 0) {
            unsigned u = __float_as_uint(best);
            u = (u & 0x80000000u) ? ~u : (u | 0x80000000u);
            unsigned long long key =
                ((unsigned long long)u << 32) | (unsigned)bestn;
            atomicMin(&g_best[m0 + ty * 4 + i], key);
        }
    }
}

// ============================================================
// K3: unpack bmu indices; emit them (as float) after the map if room
// ============================================================
__global__ void k_finalize(float* __restrict__ out, int out_size) {
    int b = blockIdx.x * blockDim.x + threadIdx.x;
    if (b < BATCH) {
        int n = (int)(unsigned)(g_best[b] & 0xFFFFFFFFull);
        g_bmu[b] = n;
        if (out_size >= NODES * FEATS + BATCH)
            out[NODES * FEATS + b] = (float)n;
    }
}

// ============================================================
// K4: update GEMM. Block = 16 nodes x 256 feats (thread d = tid).
// lr_op[b,n] recomputed on the fly from bmu[b] into smem (once each).
// acc[k] = sum_b lr_op[b, n0+k] * x[b, d];  s[k] = sum_b lr_op[b, n0+k]
// new_w = w + (acc - s * w) / BATCH
// ============================================================
__global__ void __launch_bounds__(256) k_update(const float* __restrict__ x,
                                                const float* __restrict__ w,
                                                float* __restrict__ out,
                                                int out_size) {
    __shared__ float sl[64][16];
    __shared__ float swarp[8][16];
    __shared__ float s_all[16];
    int tid = threadIdx.x;
    int n0 = blockIdx.x * 16;
    int k = tid & 15;
    int nk = n0 + k;
    float ni = (float)(nk >> 6);
    float nj = (float)(nk & 63);
    float lr = g_params[0], inv2r2 = g_params[1], r2 = g_params[2];

    float acc[16];
    #pragma unroll
    for (int kk = 0; kk < 16; kk++) acc[kk] = 0.0f;
    float spart = 0.0f;

    for (int b0 = 0; b0 < BATCH; b0 += 64) {
        __syncthreads();
        #pragma unroll
        for (int q = 0; q < 4; q++) {
            int bb = (tid >> 4) + 16 * q;
            int bmu = g_bmu[b0 + bb];
            float di = ni - (float)(bmu >> 6);
            float dj = nj - (float)(bmu & 63);
            float d2 = di * di + dj * dj;
            float v = (d2 <= r2) ? lr * __expf(-d2 * inv2r2) : 0.0f;
            sl[bb][k] = v;
            spart += v;
        }
        __syncthreads();
        #pragma unroll 4
        for (int bb = 0; bb < 64; bb++) {
            float xv = x[(size_t)(b0 + bb) * FEATS + tid];
            const float4* row = (const float4*)sl[bb];
            float4 l0 = row[0], l1 = row[1], l2 = row[2], l3 = row[3];
            acc[0]  += l0.x * xv;  acc[1]  += l0.y * xv;
            acc[2]  += l0.z * xv;  acc[3]  += l0.w * xv;
            acc[4]  += l1.x * xv;  acc[5]  += l1.y * xv;
            acc[6]  += l1.z * xv;  acc[7]  += l1.w * xv;
            acc[8]  += l2.x * xv;  acc[9]  += l2.y * xv;
            acc[10] += l2.z * xv;  acc[11] += l2.w * xv;
            acc[12] += l3.x * xv;  acc[13] += l3.y * xv;
            acc[14] += l3.z * xv;  acc[15] += l3.w * xv;
        }
    }

    // reduce spart across the 16 threads sharing each k
    spart += __shfl_xor_sync(0xFFFFFFFFu, spart, 16);
    int lane = tid & 31, warp = tid >> 5;
    if (lane < 16) swarp[warp][lane] = spart;
    __syncthreads();
    if (tid < 16) {
        float s = 0.0f;
        #pragma unroll
        for (int wv = 0; wv < 8; wv++) s += swarp[wv][tid];
        s_all[tid] = s;
    }
    __syncthreads();

    const float invB = 1.0f / (float)BATCH;
    #pragma unroll
    for (int kk = 0; kk < 16; kk++) {
        int idx = (n0 + kk) * FEATS + tid;
        if (idx < out_size) {
            float wv = w[idx];
            out[idx] = wv + (acc[kk] - s_all[kk] * wv) * invB;
        }
    }
}

// ============================================================
extern "C" void kernel_launch(void* const* d_in, const int* in_sizes, int n_in,
                              void* d_out, int out_size) {
    // identify inputs by element count (robust to metadata ordering)
    const float* x = nullptr;
    const float* w = nullptr;
    const int* iter = nullptr;
    for (int i = 0; i < n_in; i++) {
        if (in_sizes[i] == BATCH * FEATS)      x = (const float*)d_in[i];
        else if (in_sizes[i] == NODES * FEATS) w = (const float*)d_in[i];
        else if (in_sizes[i] == 1)             iter = (const int*)d_in[i];
    }
    float* out = (float*)d_out;

    k_init<<<4, 256>>>(iter);
    k_w2<<<NODES / 8, 256>>>(w);
    dim3 g1(NODES / 64, BATCH / 64);
    k_bmu<<<g1, 256>>>(x, w);
    k_finalize<<<4, 256>>>(out, out_size);
    k_update<<<NODES / 16, 256>>>(x, w, out, out_size);
}